// round 2
// baseline (speedup 1.0000x reference)
#include <cuda_runtime.h>
#include <math.h>

// ---------------------------------------------------------------------------
// Problem constants
// ---------------------------------------------------------------------------
constexpr int Bc = 12, Sc = 1024, Dc = 1024, NHc = 16;
// Dh=64, bb=2, NV=6, IH=IW=32, ROW_VIEWS=4, COL_IDX={0,2,4,5}

// ---------------------------------------------------------------------------
// Scratch (device globals; no allocation allowed)
// ---------------------------------------------------------------------------
__device__ float g_q   [12582912];
__device__ float g_k   [12582912];
__device__ float g_v   [12582912];
__device__ float g_qm  [12582912];
__device__ float g_km  [12582912];
__device__ float g_vm  [12582912];
__device__ float g_attn[12582912];
__device__ float g_main[12582912];
__device__ float g_mv  [12582912];
__device__ float g_qr  [8388608];
__device__ float g_kr  [8388608];
__device__ float g_vr  [8388608];
__device__ float g_qc  [8388608];
__device__ float g_kc  [8388608];
__device__ float g_vc  [8388608];
__device__ float g_or  [8388608];
__device__ float g_oc  [8388608];
__device__ float g_scr [16777216];    // row scores: 1024*128*128
__device__ float g_scc [16777216];    // col scores

// ---------------------------------------------------------------------------
// TF32 helpers
// ---------------------------------------------------------------------------
__device__ __forceinline__ unsigned f2tf(float x) {
    unsigned r; asm("cvt.rna.tf32.f32 %0, %1;" : "=r"(r) : "f"(x)); return r;
}

__device__ __forceinline__ void mma8(float* c, const unsigned* a, const unsigned* b) {
    asm volatile(
        "mma.sync.aligned.m16n8k8.row.col.f32.tf32.tf32.f32 "
        "{%0,%1,%2,%3},{%4,%5,%6,%7},{%8,%9},{%0,%1,%2,%3};"
        : "+f"(c[0]), "+f"(c[1]), "+f"(c[2]), "+f"(c[3])
        : "r"(a[0]), "r"(a[1]), "r"(a[2]), "r"(a[3]), "r"(b[0]), "r"(b[1]));
}

// ---------------------------------------------------------------------------
// Generic batched TF32 GEMM (unchanged, verified in round 0).
//   C = alpha * A @ B (+bias[n] +add1 +add2)
//   B_NT=true : Bmat given as (N,K) row-major (x @ W.T style)
//   B_NT=false: Bmat given as (K,N) row-major
// ---------------------------------------------------------------------------
template<int BM, int BN, int WM, int WN, bool B_NT>
__global__ void __launch_bounds__((BM/WM)*(BN/WN)*32)
gemm_tf32(const float* __restrict__ A, const float* __restrict__ Bmat,
          float* __restrict__ C,
          int K, int lda, int ldb, int ldc,
          int binner, long sAo, long sAi, long sBo, long sBi, long sCo, long sCi,
          float alpha, const float* __restrict__ bias,
          const float* __restrict__ add1, int ld1,
          const float* __restrict__ add2, int ld2)
{
    constexpr int BK  = 16;
    constexpr int NW  = (BM/WM)*(BN/WN);
    constexpr int NTH = NW * 32;
    constexpr int BMp = BM + 4, BNp = BN + 4;
    constexpr int WARPS_M = BM / WM;
    constexpr int MT  = WM / 16, NTT = WN / 8;

    __shared__ unsigned As[2][BK][BMp];
    __shared__ unsigned Bs[2][BK][BNp];

    const int tid = threadIdx.x;
    const int z   = blockIdx.z;
    const float* Ab = A    + (long)(z / binner) * sAo + (long)(z % binner) * sAi;
    const float* Bb = Bmat + (long)(z / binner) * sBo + (long)(z % binner) * sBi;
    float*       Cb = C    + (long)(z / binner) * sCo + (long)(z % binner) * sCi;

    const int m0 = blockIdx.y * BM;
    const int n0 = blockIdx.x * BN;

    const int warp = tid >> 5, lane = tid & 31;
    const int wm = (warp % WARPS_M) * WM;
    const int wn = (warp / WARPS_M) * WN;

    float acc[MT][NTT][4];
    #pragma unroll
    for (int mi = 0; mi < MT; mi++)
        #pragma unroll
        for (int ni = 0; ni < NTT; ni++)
            #pragma unroll
            for (int t = 0; t < 4; t++) acc[mi][ni][t] = 0.f;

    const int nkt = K / BK;

    auto load_tile = [&](int kt, int buf) {
        constexpr int ACH = BM * (BK/4);
        for (int i = tid; i < ACH; i += NTH) {
            int row = i / (BK/4), c4 = i % (BK/4);
            const float4 vv = *reinterpret_cast<const float4*>(
                Ab + (long)(m0 + row) * lda + kt*BK + c4*4);
            int kb = c4*4;
            As[buf][kb+0][row] = f2tf(vv.x);
            As[buf][kb+1][row] = f2tf(vv.y);
            As[buf][kb+2][row] = f2tf(vv.z);
            As[buf][kb+3][row] = f2tf(vv.w);
        }
        if (B_NT) {
            constexpr int BCH = BN * (BK/4);
            for (int i = tid; i < BCH; i += NTH) {
                int row = i / (BK/4), c4 = i % (BK/4);
                const float4 vv = *reinterpret_cast<const float4*>(
                    Bb + (long)(n0 + row) * ldb + kt*BK + c4*4);
                int kb = c4*4;
                Bs[buf][kb+0][row] = f2tf(vv.x);
                Bs[buf][kb+1][row] = f2tf(vv.y);
                Bs[buf][kb+2][row] = f2tf(vv.z);
                Bs[buf][kb+3][row] = f2tf(vv.w);
            }
        } else {
            constexpr int BCH = BK * (BN/4);
            for (int i = tid; i < BCH; i += NTH) {
                int kr = i / (BN/4), c4 = i % (BN/4);
                const float4 vv = *reinterpret_cast<const float4*>(
                    Bb + (long)(kt*BK + kr) * ldb + n0 + c4*4);
                int nb = c4*4;
                Bs[buf][kr][nb+0] = f2tf(vv.x);
                Bs[buf][kr][nb+1] = f2tf(vv.y);
                Bs[buf][kr][nb+2] = f2tf(vv.z);
                Bs[buf][kr][nb+3] = f2tf(vv.w);
            }
        }
    };

    auto compute = [&](int buf) {
        #pragma unroll
        for (int ks = 0; ks < BK/8; ks++) {
            unsigned af[MT][4], bf[NTT][2];
            #pragma unroll
            for (int mi = 0; mi < MT; mi++) {
                int r = wm + mi*16 + (lane >> 2);
                int kk = ks*8 + (lane & 3);
                af[mi][0] = As[buf][kk  ][r];
                af[mi][1] = As[buf][kk  ][r+8];
                af[mi][2] = As[buf][kk+4][r];
                af[mi][3] = As[buf][kk+4][r+8];
            }
            #pragma unroll
            for (int ni = 0; ni < NTT; ni++) {
                int cn = wn + ni*8 + (lane >> 2);
                int kk = ks*8 + (lane & 3);
                bf[ni][0] = Bs[buf][kk  ][cn];
                bf[ni][1] = Bs[buf][kk+4][cn];
            }
            #pragma unroll
            for (int mi = 0; mi < MT; mi++)
                #pragma unroll
                for (int ni = 0; ni < NTT; ni++)
                    mma8(acc[mi][ni], af[mi], bf[ni]);
        }
    };

    load_tile(0, 0);
    __syncthreads();
    for (int kt = 0; kt < nkt; kt++) {
        int buf = kt & 1;
        if (kt + 1 < nkt) load_tile(kt + 1, buf ^ 1);
        compute(buf);
        __syncthreads();
    }

    #pragma unroll
    for (int mi = 0; mi < MT; mi++) {
        #pragma unroll
        for (int ni = 0; ni < NTT; ni++) {
            int r0 = m0 + wm + mi*16 + (lane >> 2);
            int cn = n0 + wn + ni*8  + (lane & 3)*2;
            #pragma unroll
            for (int half = 0; half < 2; half++) {
                int r = r0 + half*8;
                float v0 = alpha * acc[mi][ni][half*2+0];
                float v1 = alpha * acc[mi][ni][half*2+1];
                if (bias) { v0 += bias[cn]; v1 += bias[cn+1]; }
                if (add1) { v0 += add1[(long)r*ld1 + cn]; v1 += add1[(long)r*ld1 + cn+1]; }
                if (add2) { v0 += add2[(long)r*ld2 + cn]; v1 += add2[(long)r*ld2 + cn+1]; }
                *reinterpret_cast<float2*>(Cb + (long)r*ldc + cn) = make_float2(v0, v1);
            }
        }
    }
}

// ---------------------------------------------------------------------------
// Fused flash attention for the main path.
// Layouts: q,k,v as (B,S,H*Dh) fp32. One CTA = 64 q-rows of one (b,h).
// 4 warps x 16 rows. Streams K/V in 64-token tiles, online softmax,
// P routed through smem into A-fragment layout for PV.
// grid = (S/64, B*H), block = 128. Dynamic smem = 3*64*65*4 bytes.
// ---------------------------------------------------------------------------
constexpr int F_LD   = 65;
constexpr int F_SZ   = 64 * F_LD;
constexpr int F_SMEM = 3 * F_SZ * 4;

__global__ void __launch_bounds__(128)
flash_main(const float* __restrict__ qg, const float* __restrict__ kg,
           const float* __restrict__ vg, float* __restrict__ og)
{
    extern __shared__ unsigned sm[];
    unsigned* Ks  = sm;            // [dh][token]
    unsigned* Vs  = sm + F_SZ;     // [token][dh]
    unsigned* QPs = sm + 2*F_SZ;   // Q: [dh][row] -> reused as P: [col][row]

    const int tid  = threadIdx.x;
    const int warp = tid >> 5, lane = tid & 31;
    const int t = lane & 3, g = lane >> 2;
    const int wm = warp * 16;

    const int b  = blockIdx.y >> 4;
    const int h  = blockIdx.y & 15;
    const int m0 = blockIdx.x * 64;
    const long baseQ = ((long)b*1024 + m0) * 1024 + h*64;
    const long baseKV = (long)b*1024*1024 + h*64;

    // load Q tile (scaled by 1/sqrt(64)), transposed to [dh][row]
    #pragma unroll
    for (int it = 0; it < 8; it++) {
        int i = tid + it*128;            // 0..1023
        int tok = i >> 4, d4 = i & 15;
        const float4 vv = *reinterpret_cast<const float4*>(qg + baseQ + (long)tok*1024 + d4*4);
        int dh = d4*4;
        QPs[(dh+0)*F_LD + tok] = f2tf(vv.x * 0.125f);
        QPs[(dh+1)*F_LD + tok] = f2tf(vv.y * 0.125f);
        QPs[(dh+2)*F_LD + tok] = f2tf(vv.z * 0.125f);
        QPs[(dh+3)*F_LD + tok] = f2tf(vv.w * 0.125f);
    }
    __syncthreads();

    // per-warp Q fragments (kept in registers for the whole sweep)
    unsigned af_q[8][4];
    #pragma unroll
    for (int ks = 0; ks < 8; ks++) {
        int kk = ks*8 + t;
        int r  = wm + g;
        af_q[ks][0] = QPs[kk*F_LD + r];
        af_q[ks][1] = QPs[kk*F_LD + r + 8];
        af_q[ks][2] = QPs[(kk+4)*F_LD + r];
        af_q[ks][3] = QPs[(kk+4)*F_LD + r + 8];
    }

    float oacc[8][4];
    #pragma unroll
    for (int ni = 0; ni < 8; ni++)
        #pragma unroll
        for (int c = 0; c < 4; c++) oacc[ni][c] = 0.f;
    float mrow[2] = {-1e30f, -1e30f};
    float lrow[2] = {0.f, 0.f};

    for (int kt = 0; kt < 16; kt++) {
        const long baseT = baseKV + (long)(kt*64) * 1024;
        // load K [dh][token] and V [token][dh]
        #pragma unroll
        for (int it = 0; it < 8; it++) {
            int i = tid + it*128;
            int tok = i >> 4, d4 = i & 15;
            const float4 kv = *reinterpret_cast<const float4*>(kg + baseT + (long)tok*1024 + d4*4);
            int dh = d4*4;
            Ks[(dh+0)*F_LD + tok] = f2tf(kv.x);
            Ks[(dh+1)*F_LD + tok] = f2tf(kv.y);
            Ks[(dh+2)*F_LD + tok] = f2tf(kv.z);
            Ks[(dh+3)*F_LD + tok] = f2tf(kv.w);
            const float4 vv = *reinterpret_cast<const float4*>(vg + baseT + (long)tok*1024 + d4*4);
            Vs[tok*F_LD + dh+0] = f2tf(vv.x);
            Vs[tok*F_LD + dh+1] = f2tf(vv.y);
            Vs[tok*F_LD + dh+2] = f2tf(vv.z);
            Vs[tok*F_LD + dh+3] = f2tf(vv.w);
        }
        __syncthreads();   // also protects QPs(Q) reads (first iter) / P rows (later)

        // S = Q K^T  (per warp: 16 x 64)
        float sacc[8][4];
        #pragma unroll
        for (int ni = 0; ni < 8; ni++)
            #pragma unroll
            for (int c = 0; c < 4; c++) sacc[ni][c] = 0.f;
        #pragma unroll
        for (int ks = 0; ks < 8; ks++) {
            int kk = ks*8 + t;
            #pragma unroll
            for (int ni = 0; ni < 8; ni++) {
                unsigned bf[2];
                int cn = ni*8 + g;
                bf[0] = Ks[kk*F_LD + cn];
                bf[1] = Ks[(kk+4)*F_LD + cn];
                mma8(sacc[ni], af_q[ks], bf);
            }
        }

        // online softmax update (rows: g and g+8 within warp tile)
        float mt0 = -1e30f, mt1 = -1e30f;
        #pragma unroll
        for (int ni = 0; ni < 8; ni++) {
            mt0 = fmaxf(mt0, fmaxf(sacc[ni][0], sacc[ni][1]));
            mt1 = fmaxf(mt1, fmaxf(sacc[ni][2], sacc[ni][3]));
        }
        mt0 = fmaxf(mt0, __shfl_xor_sync(0xffffffffu, mt0, 1));
        mt0 = fmaxf(mt0, __shfl_xor_sync(0xffffffffu, mt0, 2));
        mt1 = fmaxf(mt1, __shfl_xor_sync(0xffffffffu, mt1, 1));
        mt1 = fmaxf(mt1, __shfl_xor_sync(0xffffffffu, mt1, 2));
        float mn0 = fmaxf(mrow[0], mt0);
        float mn1 = fmaxf(mrow[1], mt1);
        float al0 = __expf(mrow[0] - mn0);
        float al1 = __expf(mrow[1] - mn1);
        float ps0 = 0.f, ps1 = 0.f;
        #pragma unroll
        for (int ni = 0; ni < 8; ni++) {
            sacc[ni][0] = __expf(sacc[ni][0] - mn0);
            sacc[ni][1] = __expf(sacc[ni][1] - mn0);
            sacc[ni][2] = __expf(sacc[ni][2] - mn1);
            sacc[ni][3] = __expf(sacc[ni][3] - mn1);
            ps0 += sacc[ni][0] + sacc[ni][1];
            ps1 += sacc[ni][2] + sacc[ni][3];
        }
        ps0 += __shfl_xor_sync(0xffffffffu, ps0, 1);
        ps0 += __shfl_xor_sync(0xffffffffu, ps0, 2);
        ps1 += __shfl_xor_sync(0xffffffffu, ps1, 1);
        ps1 += __shfl_xor_sync(0xffffffffu, ps1, 2);
        lrow[0] = lrow[0]*al0 + ps0;  mrow[0] = mn0;
        lrow[1] = lrow[1]*al1 + ps1;  mrow[1] = mn1;
        #pragma unroll
        for (int ni = 0; ni < 8; ni++) {
            oacc[ni][0] *= al0; oacc[ni][1] *= al0;
            oacc[ni][2] *= al1; oacc[ni][3] *= al1;
        }

        // stage P into [col][row] (warp-private rows)
        #pragma unroll
        for (int ni = 0; ni < 8; ni++) {
            int c0 = ni*8 + t*2;
            QPs[(c0  )*F_LD + wm + g    ] = f2tf(sacc[ni][0]);
            QPs[(c0+1)*F_LD + wm + g    ] = f2tf(sacc[ni][1]);
            QPs[(c0  )*F_LD + wm + g + 8] = f2tf(sacc[ni][2]);
            QPs[(c0+1)*F_LD + wm + g + 8] = f2tf(sacc[ni][3]);
        }
        __syncwarp();

        // O += P V  (per warp: 16 x 64)
        #pragma unroll
        for (int ks = 0; ks < 8; ks++) {
            int kk = ks*8 + t;
            unsigned ap[4];
            ap[0] = QPs[kk*F_LD + wm + g];
            ap[1] = QPs[kk*F_LD + wm + g + 8];
            ap[2] = QPs[(kk+4)*F_LD + wm + g];
            ap[3] = QPs[(kk+4)*F_LD + wm + g + 8];
            #pragma unroll
            for (int ni = 0; ni < 8; ni++) {
                unsigned bf[2];
                int cn = ni*8 + g;
                bf[0] = Vs[kk*F_LD + cn];
                bf[1] = Vs[(kk+4)*F_LD + cn];
                mma8(oacc[ni], ap, bf);
            }
        }
        __syncthreads();   // protect Ks/Vs before next tile's loads
    }

    // normalize + write (B,S,H*Dh)
    const float inv0 = 1.f / lrow[0];
    const float inv1 = 1.f / lrow[1];
    #pragma unroll
    for (int ni = 0; ni < 8; ni++) {
        long r0 = m0 + wm + g;
        int  cn = h*64 + ni*8 + t*2;
        *reinterpret_cast<float2*>(og + ((long)b*1024 + r0)*1024 + cn) =
            make_float2(oacc[ni][0]*inv0, oacc[ni][1]*inv0);
        *reinterpret_cast<float2*>(og + ((long)b*1024 + r0 + 8)*1024 + cn) =
            make_float2(oacc[ni][2]*inv1, oacc[ni][3]*inv1);
    }
}

// ---------------------------------------------------------------------------
// Row-wise softmax for mv path (L=128), warp per row.
// ---------------------------------------------------------------------------
template<int L>
__global__ void softmax_rows(float* __restrict__ s, long nrows) {
    constexpr int PER = L / 32;
    const int lane = threadIdx.x & 31;
    const long row = (long)blockIdx.x * (blockDim.x >> 5) + (threadIdx.x >> 5);
    if (row >= nrows) return;
    float* p = s + row * L;
    float v[PER];
    float m = -3.4e38f;
    #pragma unroll
    for (int i = 0; i < PER; i++) { v[i] = p[i*32 + lane]; m = fmaxf(m, v[i]); }
    #pragma unroll
    for (int o = 16; o; o >>= 1) m = fmaxf(m, __shfl_xor_sync(0xffffffffu, m, o));
    float sum = 0.f;
    #pragma unroll
    for (int i = 0; i < PER; i++) { v[i] = __expf(v[i] - m); sum += v[i]; }
    #pragma unroll
    for (int o = 16; o; o >>= 1) sum += __shfl_xor_sync(0xffffffffu, sum, o);
    const float inv = 1.f / sum;
    #pragma unroll
    for (int i = 0; i < PER; i++) p[i*32 + lane] = v[i] * inv;
}

// ---------------------------------------------------------------------------
// Gather kernels: materialize row/col multi-view layouts.
// ---------------------------------------------------------------------------
__global__ void gather_row_kernel(const float4* __restrict__ q,
                                  const float4* __restrict__ k,
                                  const float4* __restrict__ v,
                                  float4* __restrict__ qr,
                                  float4* __restrict__ kr,
                                  float4* __restrict__ vr) {
    int i = blockIdx.x * blockDim.x + threadIdx.x;
    if (i >= 2097152) return;
    int dh4 = i & 15;
    int t   = (i >> 4)  & 127;
    int h   = (i >> 11) & 15;
    int g   = i >> 15;
    int b2 = g >> 5, ih = g & 31;
    int rv = t >> 5, iw = t & 31;
    long src = ((long)(b2*6 + rv) * 1024 + ih*32 + iw) * 256 + h*16 + dh4;
    qr[i] = q[src]; kr[i] = k[src]; vr[i] = v[src];
}

__global__ void gather_col_kernel(const float4* __restrict__ q,
                                  const float4* __restrict__ k,
                                  const float4* __restrict__ v,
                                  float4* __restrict__ qc,
                                  float4* __restrict__ kc,
                                  float4* __restrict__ vc) {
    int i = blockIdx.x * blockDim.x + threadIdx.x;
    if (i >= 2097152) return;
    int dh4 = i & 15;
    int t2  = (i >> 4)  & 127;
    int h   = (i >> 11) & 15;
    int g2  = i >> 15;
    int b2 = g2 >> 5, iw = g2 & 31;
    int ci = t2 >> 5, ih = t2 & 31;
    const int colv[4] = {0, 2, 4, 5};
    int nv = colv[ci];
    long src = ((long)(b2*6 + nv) * 1024 + ih*32 + iw) * 256 + h*16 + dh4;
    qc[i] = q[src]; kc[i] = k[src]; vc[i] = v[src];
}

// ---------------------------------------------------------------------------
// Combine row/col attention outputs into the (B,S,D) mv tensor.
// ---------------------------------------------------------------------------
__global__ void combine_mv(const float4* __restrict__ orow,
                           const float4* __restrict__ ocol,
                           float4* __restrict__ mv) {
    int i = blockIdx.x * blockDim.x + threadIdx.x;
    if (i >= 3145728) return;
    int d4 = i & 255;
    int s  = (i >> 8) & 1023;
    int b  = i >> 18;
    int b2 = b / 6, nv = b % 6;
    int ih = s >> 5, iw = s & 31;
    int h  = d4 >> 4, dh4 = d4 & 15;

    bool has_row = (nv < 4);
    int ci = (nv == 0) ? 0 : (nv == 2) ? 1 : (nv == 4) ? 2 : (nv == 5) ? 3 : -1;

    float4 r4 = make_float4(0.f, 0.f, 0.f, 0.f);
    float4 c4 = make_float4(0.f, 0.f, 0.f, 0.f);
    if (has_row) {
        long ri = (((long)(b2*32 + ih)*16 + h)*128 + nv*32 + iw)*16 + dh4;
        r4 = orow[ri];
    }
    if (ci >= 0) {
        long cidx = (((long)(b2*32 + iw)*16 + h)*128 + ci*32 + ih)*16 + dh4;
        c4 = ocol[cidx];
    }
    float4 o;
    if (has_row && ci >= 0) {
        o.x = 0.5f*(r4.x + c4.x); o.y = 0.5f*(r4.y + c4.y);
        o.z = 0.5f*(r4.z + c4.z); o.w = 0.5f*(r4.w + c4.w);
    } else if (has_row) o = r4;
    else                o = c4;
    mv[i] = o;
}

// ---------------------------------------------------------------------------
// Launch
// ---------------------------------------------------------------------------
extern "C" void kernel_launch(void* const* d_in, const int* in_sizes, int n_in,
                              void* d_out, int out_size) {
    const float* x   = (const float*)d_in[0];
    const float* Wq  = (const float*)d_in[1];
    const float* Wk  = (const float*)d_in[2];
    const float* Wv  = (const float*)d_in[3];
    const float* Wo  = (const float*)d_in[4];
    const float* bo  = (const float*)d_in[5];
    const float* Wqm = (const float*)d_in[6];
    const float* Wkm = (const float*)d_in[7];
    const float* Wvm = (const float*)d_in[8];
    const float* Wom = (const float*)d_in[9];
    const float* bom = (const float*)d_in[10];
    float* out = (float*)d_out;

    float *q, *k, *v, *qm, *km, *vm, *attn, *maino, *mvb;
    float *qr, *kr, *vr, *qc, *kc, *vc, *orow, *ocol, *scr, *scc;
    cudaGetSymbolAddress((void**)&q,    g_q);
    cudaGetSymbolAddress((void**)&k,    g_k);
    cudaGetSymbolAddress((void**)&v,    g_v);
    cudaGetSymbolAddress((void**)&qm,   g_qm);
    cudaGetSymbolAddress((void**)&km,   g_km);
    cudaGetSymbolAddress((void**)&vm,   g_vm);
    cudaGetSymbolAddress((void**)&attn, g_attn);
    cudaGetSymbolAddress((void**)&maino,g_main);
    cudaGetSymbolAddress((void**)&mvb,  g_mv);
    cudaGetSymbolAddress((void**)&qr,   g_qr);
    cudaGetSymbolAddress((void**)&kr,   g_kr);
    cudaGetSymbolAddress((void**)&vr,   g_vr);
    cudaGetSymbolAddress((void**)&qc,   g_qc);
    cudaGetSymbolAddress((void**)&kc,   g_kc);
    cudaGetSymbolAddress((void**)&vc,   g_vc);
    cudaGetSymbolAddress((void**)&orow, g_or);
    cudaGetSymbolAddress((void**)&ocol, g_oc);
    cudaGetSymbolAddress((void**)&scr,  g_scr);
    cudaGetSymbolAddress((void**)&scc,  g_scc);

    cudaFuncSetAttribute(flash_main, cudaFuncAttributeMaxDynamicSharedMemorySize, F_SMEM);

    const float scale = 0.125f;
    dim3 gProj(Dc/128, (Bc*Sc)/128, 1);   // (8, 96)

    // 1) six input projections: (12288 x 1024 x 1024) NT
    gemm_tf32<128,128,64,32,true><<<gProj,256>>>(x, Wq,  q,  1024, 1024,1024,1024,
        1, 0,0, 0,0, 0,0, 1.f, nullptr, nullptr,0, nullptr,0);
    gemm_tf32<128,128,64,32,true><<<gProj,256>>>(x, Wk,  k,  1024, 1024,1024,1024,
        1, 0,0, 0,0, 0,0, 1.f, nullptr, nullptr,0, nullptr,0);
    gemm_tf32<128,128,64,32,true><<<gProj,256>>>(x, Wv,  v,  1024, 1024,1024,1024,
        1, 0,0, 0,0, 0,0, 1.f, nullptr, nullptr,0, nullptr,0);
    gemm_tf32<128,128,64,32,true><<<gProj,256>>>(x, Wqm, qm, 1024, 1024,1024,1024,
        1, 0,0, 0,0, 0,0, 1.f, nullptr, nullptr,0, nullptr,0);
    gemm_tf32<128,128,64,32,true><<<gProj,256>>>(x, Wkm, km, 1024, 1024,1024,1024,
        1, 0,0, 0,0, 0,0, 1.f, nullptr, nullptr,0, nullptr,0);
    gemm_tf32<128,128,64,32,true><<<gProj,256>>>(x, Wvm, vm, 1024, 1024,1024,1024,
        1, 0,0, 0,0, 0,0, 1.f, nullptr, nullptr,0, nullptr,0);

    // 2) main attention: fused flash kernel
    dim3 gF(16, Bc*NHc);
    flash_main<<<gF, 128, F_SMEM>>>(q, k, v, attn);

    // main output projection (+ bo)
    gemm_tf32<128,128,64,32,true><<<gProj,256>>>(attn, Wo, maino, 1024, 1024,1024,1024,
        1, 0,0, 0,0, 0,0, 1.f, bo, nullptr,0, nullptr,0);

    // 3) multi-view gathers
    gather_row_kernel<<<8192,256>>>((const float4*)qm, (const float4*)km, (const float4*)vm,
                                    (float4*)qr, (float4*)kr, (float4*)vr);
    gather_col_kernel<<<8192,256>>>((const float4*)qm, (const float4*)km, (const float4*)vm,
                                    (float4*)qc, (float4*)kc, (float4*)vc);

    // row attention: 1024 (batch,head) pairs, 128 tokens, Dh=64
    dim3 gMV(1, 1, 1024);
    gemm_tf32<128,128,64,32,true><<<gMV,256>>>(qr, kr, scr, 64, 64,64,128,
        1, 8192,0, 8192,0, 16384,0, scale, nullptr, nullptr,0, nullptr,0);
    softmax_rows<128><<<(1024*128)/4, 128>>>(scr, 1024L*128);
    gemm_tf32<128,64,64,32,false><<<gMV,128>>>(scr, vr, orow, 128, 128,64,64,
        1, 16384,0, 8192,0, 8192,0, 1.f, nullptr, nullptr,0, nullptr,0);

    // col attention
    gemm_tf32<128,128,64,32,true><<<gMV,256>>>(qc, kc, scc, 64, 64,64,128,
        1, 8192,0, 8192,0, 16384,0, scale, nullptr, nullptr,0, nullptr,0);
    softmax_rows<128><<<(1024*128)/4, 128>>>(scc, 1024L*128);
    gemm_tf32<128,64,64,32,false><<<gMV,128>>>(scc, vc, ocol, 128, 128,64,64,
        1, 16384,0, 8192,0, 8192,0, 1.f, nullptr, nullptr,0, nullptr,0);

    // 4) combine views into (B,S,D)
    combine_mv<<<12288,256>>>((const float4*)orow, (const float4*)ocol, (float4*)mvb);

    // 5) mv output projection, fused final sum: out = mv@Wom^T + bom + main + x
    gemm_tf32<128,128,64,32,true><<<gProj,256>>>(mvb, Wom, out, 1024, 1024,1024,1024,
        1, 0,0, 0,0, 0,0, 1.f, bom, maino, 1024, x, 1024);
}

// round 4
// speedup vs baseline: 1.5673x; 1.5673x over previous
#include <cuda_runtime.h>
#include <math.h>
#include <stdint.h>

// ---------------------------------------------------------------------------
// Problem constants
// ---------------------------------------------------------------------------
constexpr int Bc = 12, Sc = 1024, Dc = 1024, NHc = 16;

// ---------------------------------------------------------------------------
// Scratch (device globals; no allocation allowed)
// ---------------------------------------------------------------------------
__device__ float g_q   [12582912];
__device__ float g_k   [12582912];
__device__ float g_v   [12582912];
__device__ float g_qm  [12582912];
__device__ float g_km  [12582912];
__device__ float g_vm  [12582912];
__device__ float g_attn[12582912];
__device__ float g_main[12582912];
__device__ float g_mv  [12582912];
__device__ float g_qr  [8388608];
__device__ float g_kr  [8388608];
__device__ float g_vr  [8388608];
__device__ float g_qc  [8388608];
__device__ float g_kc  [8388608];
__device__ float g_vc  [8388608];
__device__ float g_or  [8388608];
__device__ float g_oc  [8388608];
__device__ float g_scr [16777216];
__device__ float g_scc [16777216];

// ---------------------------------------------------------------------------
// Helpers
// ---------------------------------------------------------------------------
__device__ __forceinline__ unsigned f2tf(float x) {
    unsigned r; asm("cvt.rna.tf32.f32 %0, %1;" : "=r"(r) : "f"(x)); return r;
}

__device__ __forceinline__ void mma8(float* c, const unsigned* a, const unsigned* b) {
    asm volatile(
        "mma.sync.aligned.m16n8k8.row.col.f32.tf32.tf32.f32 "
        "{%0,%1,%2,%3},{%4,%5,%6,%7},{%8,%9},{%0,%1,%2,%3};"
        : "+f"(c[0]), "+f"(c[1]), "+f"(c[2]), "+f"(c[3])
        : "r"(a[0]), "r"(a[1]), "r"(a[2]), "r"(a[3]), "r"(b[0]), "r"(b[1]));
}

__device__ __forceinline__ uint32_t smem_u32(const void* p) {
    uint32_t a;
    asm("{ .reg .u64 t; cvta.to.shared.u64 t, %1; cvt.u32.u64 %0, t; }"
        : "=r"(a) : "l"(p));
    return a;
}

__device__ __forceinline__ void cp16(uint32_t dst, const void* src) {
    asm volatile("cp.async.cg.shared.global [%0], [%1], 16;"
                 :: "r"(dst), "l"(src) : "memory");
}

// ---------------------------------------------------------------------------
// Big NT GEMM on mma.sync tf32 with cp.async 4-stage pipeline.
//   C[M,1024] = A[M,1024] @ B(1024x1024 N,K row-major)^T  (+bias +add1 +add2)
// Raw f32 bits are fed to the tf32 mma (hardware RZ truncation) — no cvt,
// no register staging, no STS. Smem layout: per stage, A then B, each
// 128 rows x 20 words (16 data + 4 pad). Stride 20 makes all fragment
// loads conflict-free (20*g + t covers all 32 banks).
// grid = (1024/128, M/128), block = 256. Dyn smem = 4 * 20480 = 81920 B.
// ---------------------------------------------------------------------------
constexpr int BG_STAGE_B = 2 * 128 * 20 * 4;      // 20480 bytes per stage
constexpr int BG_SMEM    = 4 * BG_STAGE_B;        // 81920

__global__ void __launch_bounds__(256, 2)
gemm_big(const float* __restrict__ A, const float* __restrict__ B,
         float* __restrict__ C,
         const float* __restrict__ bias,
         const float* __restrict__ add1, const float* __restrict__ add2)
{
    extern __shared__ char smem[];
    const uint32_t sb = smem_u32(smem);

    const int tid = threadIdx.x;
    const int warp = tid >> 5, lane = tid & 31;
    const int g = lane >> 2, t = lane & 3;
    const int m0 = blockIdx.y * 128;
    const int n0 = blockIdx.x * 128;
    // 8 warps: 2 along M (WM=64), 4 along N (WN=32)
    const int wm = (warp & 1) * 64;
    const int wn = (warp >> 1) * 32;

    float acc[4][4][4];
    #pragma unroll
    for (int mi = 0; mi < 4; mi++)
        #pragma unroll
        for (int ni = 0; ni < 4; ni++)
            #pragma unroll
            for (int c = 0; c < 4; c++) acc[mi][ni][c] = 0.f;

    // per-stage: A at +0 (128 rows x 80B), B at +10240
    auto load_chunk = [&](int kt, int s) {
        const uint32_t ab = sb + s * BG_STAGE_B;
        const uint32_t bb = ab + 128 * 80;
        #pragma unroll
        for (int half = 0; half < 2; half++) {
            int idx = tid + half * 256;          // 0..511
            int row = idx >> 2, c4 = idx & 3;
            uint32_t so = row * 80 + c4 * 16;
            cp16(ab + so, A + (long)(m0 + row) * 1024 + kt * 16 + c4 * 4);
            cp16(bb + so, B + (long)(n0 + row) * 1024 + kt * 16 + c4 * 4);
        }
    };

    load_chunk(0, 0); asm volatile("cp.async.commit_group;" ::: "memory");
    load_chunk(1, 1); asm volatile("cp.async.commit_group;" ::: "memory");
    load_chunk(2, 2); asm volatile("cp.async.commit_group;" ::: "memory");
    load_chunk(3, 3); asm volatile("cp.async.commit_group;" ::: "memory");

    for (int kt = 0; kt < 64; kt++) {
        const int s = kt & 3;
        asm volatile("cp.async.wait_group 3;" ::: "memory");
        __syncthreads();

        const unsigned* As_ = (const unsigned*)(smem + s * BG_STAGE_B);
        const unsigned* Bs_ = As_ + 128 * 20;
        #pragma unroll
        for (int ks = 0; ks < 2; ks++) {
            unsigned af[4][4], bf[4][2];
            const int k0 = ks * 8 + t;
            #pragma unroll
            for (int mi = 0; mi < 4; mi++) {
                int r = wm + mi * 16 + g;
                af[mi][0] = As_[r * 20 + k0];
                af[mi][1] = As_[(r + 8) * 20 + k0];
                af[mi][2] = As_[r * 20 + k0 + 4];
                af[mi][3] = As_[(r + 8) * 20 + k0 + 4];
            }
            #pragma unroll
            for (int ni = 0; ni < 4; ni++) {
                int cn = wn + ni * 8 + g;
                bf[ni][0] = Bs_[cn * 20 + k0];
                bf[ni][1] = Bs_[cn * 20 + k0 + 4];
            }
            #pragma unroll
            for (int mi = 0; mi < 4; mi++)
                #pragma unroll
                for (int ni = 0; ni < 4; ni++)
                    mma8(acc[mi][ni], af[mi], bf[ni]);
        }
        __syncthreads();

        if (kt + 4 < 64) load_chunk(kt + 4, s);
        asm volatile("cp.async.commit_group;" ::: "memory");
    }

    // epilogue: direct reg -> gmem, fused bias/add1/add2
    #pragma unroll
    for (int mi = 0; mi < 4; mi++) {
        #pragma unroll
        for (int ni = 0; ni < 4; ni++) {
            int r0 = m0 + wm + mi * 16 + g;
            int cn = n0 + wn + ni * 8 + t * 2;
            #pragma unroll
            for (int half = 0; half < 2; half++) {
                int r = r0 + half * 8;
                float v0 = acc[mi][ni][half * 2 + 0];
                float v1 = acc[mi][ni][half * 2 + 1];
                if (bias) { v0 += bias[cn]; v1 += bias[cn + 1]; }
                if (add1) {
                    const float2 a2 = *reinterpret_cast<const float2*>(add1 + (long)r * 1024 + cn);
                    v0 += a2.x; v1 += a2.y;
                }
                if (add2) {
                    const float2 a2 = *reinterpret_cast<const float2*>(add2 + (long)r * 1024 + cn);
                    v0 += a2.x; v1 += a2.y;
                }
                *reinterpret_cast<float2*>(C + (long)r * 1024 + cn) = make_float2(v0, v1);
            }
        }
    }
}

// ---------------------------------------------------------------------------
// Legacy TF32 GEMM (mv-path small GEMMs only; verified round 2).
// ---------------------------------------------------------------------------
template<int BM, int BN, int WM, int WN, bool B_NT>
__global__ void __launch_bounds__((BM/WM)*(BN/WN)*32)
gemm_tf32(const float* __restrict__ A, const float* __restrict__ Bmat,
          float* __restrict__ C,
          int K, int lda, int ldb, int ldc,
          int binner, long sAo, long sAi, long sBo, long sBi, long sCo, long sCi,
          float alpha)
{
    constexpr int BK  = 16;
    constexpr int NW  = (BM/WM)*(BN/WN);
    constexpr int NTH = NW * 32;
    constexpr int BMp = BM + 4, BNp = BN + 4;
    constexpr int WARPS_M = BM / WM;
    constexpr int MT  = WM / 16, NTT = WN / 8;

    __shared__ unsigned As[2][BK][BMp];
    __shared__ unsigned Bs[2][BK][BNp];

    const int tid = threadIdx.x;
    const int z   = blockIdx.z;
    const float* Ab = A    + (long)(z / binner) * sAo + (long)(z % binner) * sAi;
    const float* Bb = Bmat + (long)(z / binner) * sBo + (long)(z % binner) * sBi;
    float*       Cb = C    + (long)(z / binner) * sCo + (long)(z % binner) * sCi;

    const int m0 = blockIdx.y * BM;
    const int n0 = blockIdx.x * BN;

    const int warp = tid >> 5, lane = tid & 31;
    const int wm = (warp % WARPS_M) * WM;
    const int wn = (warp / WARPS_M) * WN;

    float acc[MT][NTT][4];
    #pragma unroll
    for (int mi = 0; mi < MT; mi++)
        #pragma unroll
        for (int ni = 0; ni < NTT; ni++)
            #pragma unroll
            for (int t = 0; t < 4; t++) acc[mi][ni][t] = 0.f;

    const int nkt = K / BK;

    auto load_tile = [&](int kt, int buf) {
        constexpr int ACH = BM * (BK/4);
        for (int i = tid; i < ACH; i += NTH) {
            int row = i / (BK/4), c4 = i % (BK/4);
            const float4 vv = *reinterpret_cast<const float4*>(
                Ab + (long)(m0 + row) * lda + kt*BK + c4*4);
            int kb = c4*4;
            As[buf][kb+0][row] = f2tf(vv.x);
            As[buf][kb+1][row] = f2tf(vv.y);
            As[buf][kb+2][row] = f2tf(vv.z);
            As[buf][kb+3][row] = f2tf(vv.w);
        }
        if (B_NT) {
            constexpr int BCH = BN * (BK/4);
            for (int i = tid; i < BCH; i += NTH) {
                int row = i / (BK/4), c4 = i % (BK/4);
                const float4 vv = *reinterpret_cast<const float4*>(
                    Bb + (long)(n0 + row) * ldb + kt*BK + c4*4);
                int kb = c4*4;
                Bs[buf][kb+0][row] = f2tf(vv.x);
                Bs[buf][kb+1][row] = f2tf(vv.y);
                Bs[buf][kb+2][row] = f2tf(vv.z);
                Bs[buf][kb+3][row] = f2tf(vv.w);
            }
        } else {
            constexpr int BCH = BK * (BN/4);
            for (int i = tid; i < BCH; i += NTH) {
                int kr = i / (BN/4), c4 = i % (BN/4);
                const float4 vv = *reinterpret_cast<const float4*>(
                    Bb + (long)(kt*BK + kr) * ldb + n0 + c4*4);
                int nb = c4*4;
                Bs[buf][kr][nb+0] = f2tf(vv.x);
                Bs[buf][kr][nb+1] = f2tf(vv.y);
                Bs[buf][kr][nb+2] = f2tf(vv.z);
                Bs[buf][kr][nb+3] = f2tf(vv.w);
            }
        }
    };

    auto compute = [&](int buf) {
        #pragma unroll
        for (int ks = 0; ks < BK/8; ks++) {
            unsigned af[MT][4], bf[NTT][2];
            #pragma unroll
            for (int mi = 0; mi < MT; mi++) {
                int r = wm + mi*16 + (lane >> 2);
                int kk = ks*8 + (lane & 3);
                af[mi][0] = As[buf][kk  ][r];
                af[mi][1] = As[buf][kk  ][r+8];
                af[mi][2] = As[buf][kk+4][r];
                af[mi][3] = As[buf][kk+4][r+8];
            }
            #pragma unroll
            for (int ni = 0; ni < NTT; ni++) {
                int cn = wn + ni*8 + (lane >> 2);
                int kk = ks*8 + (lane & 3);
                bf[ni][0] = Bs[buf][kk  ][cn];
                bf[ni][1] = Bs[buf][kk+4][cn];
            }
            #pragma unroll
            for (int mi = 0; mi < MT; mi++)
                #pragma unroll
                for (int ni = 0; ni < NTT; ni++)
                    mma8(acc[mi][ni], af[mi], bf[ni]);
        }
    };

    load_tile(0, 0);
    __syncthreads();
    for (int kt = 0; kt < nkt; kt++) {
        int buf = kt & 1;
        if (kt + 1 < nkt) load_tile(kt + 1, buf ^ 1);
        compute(buf);
        __syncthreads();
    }

    #pragma unroll
    for (int mi = 0; mi < MT; mi++) {
        #pragma unroll
        for (int ni = 0; ni < NTT; ni++) {
            int r0 = m0 + wm + mi*16 + (lane >> 2);
            int cn = n0 + wn + ni*8  + (lane & 3)*2;
            #pragma unroll
            for (int half = 0; half < 2; half++) {
                int r = r0 + half*8;
                float v0 = alpha * acc[mi][ni][half*2+0];
                float v1 = alpha * acc[mi][ni][half*2+1];
                *reinterpret_cast<float2*>(Cb + (long)r*ldc + cn) = make_float2(v0, v1);
            }
        }
    }
}

// ---------------------------------------------------------------------------
// Fused flash attention for the main path (verified round 2).
// ---------------------------------------------------------------------------
constexpr int F_LD   = 65;
constexpr int F_SZ   = 64 * F_LD;
constexpr int F_SMEM = 3 * F_SZ * 4;

__global__ void __launch_bounds__(128)
flash_main(const float* __restrict__ qg, const float* __restrict__ kg,
           const float* __restrict__ vg, float* __restrict__ og)
{
    extern __shared__ unsigned sm[];
    unsigned* Ks  = sm;
    unsigned* Vs  = sm + F_SZ;
    unsigned* QPs = sm + 2*F_SZ;

    const int tid  = threadIdx.x;
    const int warp = tid >> 5, lane = tid & 31;
    const int t = lane & 3, g = lane >> 2;
    const int wm = warp * 16;

    const int b  = blockIdx.y >> 4;
    const int h  = blockIdx.y & 15;
    const int m0 = blockIdx.x * 64;
    const long baseQ = ((long)b*1024 + m0) * 1024 + h*64;
    const long baseKV = (long)b*1024*1024 + h*64;

    #pragma unroll
    for (int it = 0; it < 8; it++) {
        int i = tid + it*128;
        int tok = i >> 4, d4 = i & 15;
        const float4 vv = *reinterpret_cast<const float4*>(qg + baseQ + (long)tok*1024 + d4*4);
        int dh = d4*4;
        QPs[(dh+0)*F_LD + tok] = f2tf(vv.x * 0.125f);
        QPs[(dh+1)*F_LD + tok] = f2tf(vv.y * 0.125f);
        QPs[(dh+2)*F_LD + tok] = f2tf(vv.z * 0.125f);
        QPs[(dh+3)*F_LD + tok] = f2tf(vv.w * 0.125f);
    }
    __syncthreads();

    unsigned af_q[8][4];
    #pragma unroll
    for (int ks = 0; ks < 8; ks++) {
        int kk = ks*8 + t;
        int r  = wm + g;
        af_q[ks][0] = QPs[kk*F_LD + r];
        af_q[ks][1] = QPs[kk*F_LD + r + 8];
        af_q[ks][2] = QPs[(kk+4)*F_LD + r];
        af_q[ks][3] = QPs[(kk+4)*F_LD + r + 8];
    }

    float oacc[8][4];
    #pragma unroll
    for (int ni = 0; ni < 8; ni++)
        #pragma unroll
        for (int c = 0; c < 4; c++) oacc[ni][c] = 0.f;
    float mrow[2] = {-1e30f, -1e30f};
    float lrow[2] = {0.f, 0.f};

    for (int kt = 0; kt < 16; kt++) {
        const long baseT = baseKV + (long)(kt*64) * 1024;
        #pragma unroll
        for (int it = 0; it < 8; it++) {
            int i = tid + it*128;
            int tok = i >> 4, d4 = i & 15;
            const float4 kv = *reinterpret_cast<const float4*>(kg + baseT + (long)tok*1024 + d4*4);
            int dh = d4*4;
            Ks[(dh+0)*F_LD + tok] = f2tf(kv.x);
            Ks[(dh+1)*F_LD + tok] = f2tf(kv.y);
            Ks[(dh+2)*F_LD + tok] = f2tf(kv.z);
            Ks[(dh+3)*F_LD + tok] = f2tf(kv.w);
            const float4 vv = *reinterpret_cast<const float4*>(vg + baseT + (long)tok*1024 + d4*4);
            Vs[tok*F_LD + dh+0] = f2tf(vv.x);
            Vs[tok*F_LD + dh+1] = f2tf(vv.y);
            Vs[tok*F_LD + dh+2] = f2tf(vv.z);
            Vs[tok*F_LD + dh+3] = f2tf(vv.w);
        }
        __syncthreads();

        float sacc[8][4];
        #pragma unroll
        for (int ni = 0; ni < 8; ni++)
            #pragma unroll
            for (int c = 0; c < 4; c++) sacc[ni][c] = 0.f;
        #pragma unroll
        for (int ks = 0; ks < 8; ks++) {
            int kk = ks*8 + t;
            #pragma unroll
            for (int ni = 0; ni < 8; ni++) {
                unsigned bf[2];
                int cn = ni*8 + g;
                bf[0] = Ks[kk*F_LD + cn];
                bf[1] = Ks[(kk+4)*F_LD + cn];
                mma8(sacc[ni], af_q[ks], bf);
            }
        }

        float mt0 = -1e30f, mt1 = -1e30f;
        #pragma unroll
        for (int ni = 0; ni < 8; ni++) {
            mt0 = fmaxf(mt0, fmaxf(sacc[ni][0], sacc[ni][1]));
            mt1 = fmaxf(mt1, fmaxf(sacc[ni][2], sacc[ni][3]));
        }
        mt0 = fmaxf(mt0, __shfl_xor_sync(0xffffffffu, mt0, 1));
        mt0 = fmaxf(mt0, __shfl_xor_sync(0xffffffffu, mt0, 2));
        mt1 = fmaxf(mt1, __shfl_xor_sync(0xffffffffu, mt1, 1));
        mt1 = fmaxf(mt1, __shfl_xor_sync(0xffffffffu, mt1, 2));
        float mn0 = fmaxf(mrow[0], mt0);
        float mn1 = fmaxf(mrow[1], mt1);
        float al0 = __expf(mrow[0] - mn0);
        float al1 = __expf(mrow[1] - mn1);
        float ps0 = 0.f, ps1 = 0.f;
        #pragma unroll
        for (int ni = 0; ni < 8; ni++) {
            sacc[ni][0] = __expf(sacc[ni][0] - mn0);
            sacc[ni][1] = __expf(sacc[ni][1] - mn0);
            sacc[ni][2] = __expf(sacc[ni][2] - mn1);
            sacc[ni][3] = __expf(sacc[ni][3] - mn1);
            ps0 += sacc[ni][0] + sacc[ni][1];
            ps1 += sacc[ni][2] + sacc[ni][3];
        }
        ps0 += __shfl_xor_sync(0xffffffffu, ps0, 1);
        ps0 += __shfl_xor_sync(0xffffffffu, ps0, 2);
        ps1 += __shfl_xor_sync(0xffffffffu, ps1, 1);
        ps1 += __shfl_xor_sync(0xffffffffu, ps1, 2);
        lrow[0] = lrow[0]*al0 + ps0;  mrow[0] = mn0;
        lrow[1] = lrow[1]*al1 + ps1;  mrow[1] = mn1;
        #pragma unroll
        for (int ni = 0; ni < 8; ni++) {
            oacc[ni][0] *= al0; oacc[ni][1] *= al0;
            oacc[ni][2] *= al1; oacc[ni][3] *= al1;
        }

        #pragma unroll
        for (int ni = 0; ni < 8; ni++) {
            int c0 = ni*8 + t*2;
            QPs[(c0  )*F_LD + wm + g    ] = f2tf(sacc[ni][0]);
            QPs[(c0+1)*F_LD + wm + g    ] = f2tf(sacc[ni][1]);
            QPs[(c0  )*F_LD + wm + g + 8] = f2tf(sacc[ni][2]);
            QPs[(c0+1)*F_LD + wm + g + 8] = f2tf(sacc[ni][3]);
        }
        __syncwarp();

        #pragma unroll
        for (int ks = 0; ks < 8; ks++) {
            int kk = ks*8 + t;
            unsigned ap[4];
            ap[0] = QPs[kk*F_LD + wm + g];
            ap[1] = QPs[kk*F_LD + wm + g + 8];
            ap[2] = QPs[(kk+4)*F_LD + wm + g];
            ap[3] = QPs[(kk+4)*F_LD + wm + g + 8];
            #pragma unroll
            for (int ni = 0; ni < 8; ni++) {
                unsigned bf[2];
                int cn = ni*8 + g;
                bf[0] = Vs[kk*F_LD + cn];
                bf[1] = Vs[(kk+4)*F_LD + cn];
                mma8(oacc[ni], ap, bf);
            }
        }
        __syncthreads();
    }

    const float inv0 = 1.f / lrow[0];
    const float inv1 = 1.f / lrow[1];
    #pragma unroll
    for (int ni = 0; ni < 8; ni++) {
        long r0 = m0 + wm + g;
        int  cn = h*64 + ni*8 + t*2;
        *reinterpret_cast<float2*>(og + ((long)b*1024 + r0)*1024 + cn) =
            make_float2(oacc[ni][0]*inv0, oacc[ni][1]*inv0);
        *reinterpret_cast<float2*>(og + ((long)b*1024 + r0 + 8)*1024 + cn) =
            make_float2(oacc[ni][2]*inv1, oacc[ni][3]*inv1);
    }
}

// ---------------------------------------------------------------------------
// Row-wise softmax for mv path (L=128), warp per row.
// ---------------------------------------------------------------------------
template<int L>
__global__ void softmax_rows(float* __restrict__ s, long nrows) {
    constexpr int PER = L / 32;
    const int lane = threadIdx.x & 31;
    const long row = (long)blockIdx.x * (blockDim.x >> 5) + (threadIdx.x >> 5);
    if (row >= nrows) return;
    float* p = s + row * L;
    float v[PER];
    float m = -3.4e38f;
    #pragma unroll
    for (int i = 0; i < PER; i++) { v[i] = p[i*32 + lane]; m = fmaxf(m, v[i]); }
    #pragma unroll
    for (int o = 16; o; o >>= 1) m = fmaxf(m, __shfl_xor_sync(0xffffffffu, m, o));
    float sum = 0.f;
    #pragma unroll
    for (int i = 0; i < PER; i++) { v[i] = __expf(v[i] - m); sum += v[i]; }
    #pragma unroll
    for (int o = 16; o; o >>= 1) sum += __shfl_xor_sync(0xffffffffu, sum, o);
    const float inv = 1.f / sum;
    #pragma unroll
    for (int i = 0; i < PER; i++) p[i*32 + lane] = v[i] * inv;
}

// ---------------------------------------------------------------------------
// Gather / combine kernels for the multi-view path (verified round 2).
// ---------------------------------------------------------------------------
__global__ void gather_row_kernel(const float4* __restrict__ q,
                                  const float4* __restrict__ k,
                                  const float4* __restrict__ v,
                                  float4* __restrict__ qr,
                                  float4* __restrict__ kr,
                                  float4* __restrict__ vr) {
    int i = blockIdx.x * blockDim.x + threadIdx.x;
    if (i >= 2097152) return;
    int dh4 = i & 15;
    int t   = (i >> 4)  & 127;
    int h   = (i >> 11) & 15;
    int g   = i >> 15;
    int b2 = g >> 5, ih = g & 31;
    int rv = t >> 5, iw = t & 31;
    long src = ((long)(b2*6 + rv) * 1024 + ih*32 + iw) * 256 + h*16 + dh4;
    qr[i] = q[src]; kr[i] = k[src]; vr[i] = v[src];
}

__global__ void gather_col_kernel(const float4* __restrict__ q,
                                  const float4* __restrict__ k,
                                  const float4* __restrict__ v,
                                  float4* __restrict__ qc,
                                  float4* __restrict__ kc,
                                  float4* __restrict__ vc) {
    int i = blockIdx.x * blockDim.x + threadIdx.x;
    if (i >= 2097152) return;
    int dh4 = i & 15;
    int t2  = (i >> 4)  & 127;
    int h   = (i >> 11) & 15;
    int g2  = i >> 15;
    int b2 = g2 >> 5, iw = g2 & 31;
    int ci = t2 >> 5, ih = t2 & 31;
    const int colv[4] = {0, 2, 4, 5};
    int nv = colv[ci];
    long src = ((long)(b2*6 + nv) * 1024 + ih*32 + iw) * 256 + h*16 + dh4;
    qc[i] = q[src]; kc[i] = k[src]; vc[i] = v[src];
}

__global__ void combine_mv(const float4* __restrict__ orow,
                           const float4* __restrict__ ocol,
                           float4* __restrict__ mv) {
    int i = blockIdx.x * blockDim.x + threadIdx.x;
    if (i >= 3145728) return;
    int d4 = i & 255;
    int s  = (i >> 8) & 1023;
    int b  = i >> 18;
    int b2 = b / 6, nv = b % 6;
    int ih = s >> 5, iw = s & 31;
    int h  = d4 >> 4, dh4 = d4 & 15;

    bool has_row = (nv < 4);
    int ci = (nv == 0) ? 0 : (nv == 2) ? 1 : (nv == 4) ? 2 : (nv == 5) ? 3 : -1;

    float4 r4 = make_float4(0.f, 0.f, 0.f, 0.f);
    float4 c4 = make_float4(0.f, 0.f, 0.f, 0.f);
    if (has_row) {
        long ri = (((long)(b2*32 + ih)*16 + h)*128 + nv*32 + iw)*16 + dh4;
        r4 = orow[ri];
    }
    if (ci >= 0) {
        long cidx = (((long)(b2*32 + iw)*16 + h)*128 + ci*32 + ih)*16 + dh4;
        c4 = ocol[cidx];
    }
    float4 o;
    if (has_row && ci >= 0) {
        o.x = 0.5f*(r4.x + c4.x); o.y = 0.5f*(r4.y + c4.y);
        o.z = 0.5f*(r4.z + c4.z); o.w = 0.5f*(r4.w + c4.w);
    } else if (has_row) o = r4;
    else                o = c4;
    mv[i] = o;
}

// ---------------------------------------------------------------------------
// Launch
// ---------------------------------------------------------------------------
extern "C" void kernel_launch(void* const* d_in, const int* in_sizes, int n_in,
                              void* d_out, int out_size) {
    const float* x   = (const float*)d_in[0];
    const float* Wq  = (const float*)d_in[1];
    const float* Wk  = (const float*)d_in[2];
    const float* Wv  = (const float*)d_in[3];
    const float* Wo  = (const float*)d_in[4];
    const float* bo  = (const float*)d_in[5];
    const float* Wqm = (const float*)d_in[6];
    const float* Wkm = (const float*)d_in[7];
    const float* Wvm = (const float*)d_in[8];
    const float* Wom = (const float*)d_in[9];
    const float* bom = (const float*)d_in[10];
    float* out = (float*)d_out;

    float *q, *k, *v, *qm, *km, *vm, *attn, *maino, *mvb;
    float *qr, *kr, *vr, *qc, *kc, *vc, *orow, *ocol, *scr, *scc;
    cudaGetSymbolAddress((void**)&q,    g_q);
    cudaGetSymbolAddress((void**)&k,    g_k);
    cudaGetSymbolAddress((void**)&v,    g_v);
    cudaGetSymbolAddress((void**)&qm,   g_qm);
    cudaGetSymbolAddress((void**)&km,   g_km);
    cudaGetSymbolAddress((void**)&vm,   g_vm);
    cudaGetSymbolAddress((void**)&attn, g_attn);
    cudaGetSymbolAddress((void**)&maino,g_main);
    cudaGetSymbolAddress((void**)&mvb,  g_mv);
    cudaGetSymbolAddress((void**)&qr,   g_qr);
    cudaGetSymbolAddress((void**)&kr,   g_kr);
    cudaGetSymbolAddress((void**)&vr,   g_vr);
    cudaGetSymbolAddress((void**)&qc,   g_qc);
    cudaGetSymbolAddress((void**)&kc,   g_kc);
    cudaGetSymbolAddress((void**)&vc,   g_vc);
    cudaGetSymbolAddress((void**)&orow, g_or);
    cudaGetSymbolAddress((void**)&ocol, g_oc);
    cudaGetSymbolAddress((void**)&scr,  g_scr);
    cudaGetSymbolAddress((void**)&scc,  g_scc);

    cudaFuncSetAttribute(flash_main, cudaFuncAttributeMaxDynamicSharedMemorySize, F_SMEM);
    cudaFuncSetAttribute(gemm_big,   cudaFuncAttributeMaxDynamicSharedMemorySize, BG_SMEM);

    const float scale = 0.125f;
    dim3 gBG(8, 96);    // (N/128, M/128)

    // 1) six input projections (cp.async pipelined mma.sync)
    gemm_big<<<gBG, 256, BG_SMEM>>>(x, Wq,  q,  nullptr, nullptr, nullptr);
    gemm_big<<<gBG, 256, BG_SMEM>>>(x, Wk,  k,  nullptr, nullptr, nullptr);
    gemm_big<<<gBG, 256, BG_SMEM>>>(x, Wv,  v,  nullptr, nullptr, nullptr);
    gemm_big<<<gBG, 256, BG_SMEM>>>(x, Wqm, qm, nullptr, nullptr, nullptr);
    gemm_big<<<gBG, 256, BG_SMEM>>>(x, Wkm, km, nullptr, nullptr, nullptr);
    gemm_big<<<gBG, 256, BG_SMEM>>>(x, Wvm, vm, nullptr, nullptr, nullptr);

    // 2) main attention (fused flash)
    dim3 gF(16, Bc*NHc);
    flash_main<<<gF, 128, F_SMEM>>>(q, k, v, attn);

    // main output projection (+ bo)
    gemm_big<<<gBG, 256, BG_SMEM>>>(attn, Wo, maino, bo, nullptr, nullptr);

    // 3) multi-view gathers
    gather_row_kernel<<<8192,256>>>((const float4*)qm, (const float4*)km, (const float4*)vm,
                                    (float4*)qr, (float4*)kr, (float4*)vr);
    gather_col_kernel<<<8192,256>>>((const float4*)qm, (const float4*)km, (const float4*)vm,
                                    (float4*)qc, (float4*)kc, (float4*)vc);

    // row attention: 1024 (batch,head) pairs, 128 tokens, Dh=64
    dim3 gMV(1, 1, 1024);
    gemm_tf32<128,128,64,32,true><<<gMV,256>>>(qr, kr, scr, 64, 64,64,128,
        1, 8192,0, 8192,0, 16384,0, scale);
    softmax_rows<128><<<(1024*128)/4, 128>>>(scr, 1024L*128);
    gemm_tf32<128,64,64,32,false><<<gMV,128>>>(scr, vr, orow, 128, 128,64,64,
        1, 16384,0, 8192,0, 8192,0, 1.f);

    // col attention
    gemm_tf32<128,128,64,32,true><<<gMV,256>>>(qc, kc, scc, 64, 64,64,128,
        1, 8192,0, 8192,0, 16384,0, scale);
    softmax_rows<128><<<(1024*128)/4, 128>>>(scc, 1024L*128);
    gemm_tf32<128,64,64,32,false><<<gMV,128>>>(scc, vc, ocol, 128, 128,64,64,
        1, 16384,0, 8192,0, 8192,0, 1.f);

    // 4) combine views into (B,S,D)
    combine_mv<<<12288,256>>>((const float4*)orow, (const float4*)ocol, (float4*)mvb);

    // 5) mv output projection, fused final sum: out = mv@Wom^T + bom + main + x
    gemm_big<<<gBG, 256, BG_SMEM>>>(mvb, Wom, out, bom, maino, x);
}